// round 1
// baseline (speedup 1.0000x reference)
#include <cuda_runtime.h>
#include <math.h>

#define BB 2
#define SS 2048
#define DD 1024
#define HH 16
#define DK 64
#define MM (BB*SS)   // 4096

// ---------------- scratch (static device memory; no allocations) ----------------
__device__ float g_Qraw[BB*SS*DD];
__device__ float g_Kraw[BB*SS*DD];
__device__ float g_Vraw[BB*SS*DD];
__device__ float g_Qh[BB*SS*DD];   // [B,H,S,DK]
__device__ float g_Kh[BB*SS*DD];
__device__ float g_Vh[BB*SS*DD];
__device__ float g_attn[BB*SS*DD]; // [B,S,D]

// ---------------- GEMM: C[4096,1024] = A[4096,1024] @ W[1024,1024] ----------------
// 64x64 block tile, 256 threads, 4x4 per thread, K-tile 16.
__global__ void gemm_kernel(const float* __restrict__ A, const float* __restrict__ W,
                            float* __restrict__ C)
{
    const int K = 1024, N = 1024;
    __shared__ float As[64][17];
    __shared__ float Bs[16][64];

    int tx = threadIdx.x & 15;     // 0..15
    int ty = threadIdx.x >> 4;     // 0..15
    int row0 = blockIdx.y * 64;
    int col0 = blockIdx.x * 64;

    float acc[4][4] = {};

    for (int k0 = 0; k0 < K; k0 += 16) {
        // load A tile 64x16
        #pragma unroll
        for (int i = threadIdx.x; i < 64 * 16; i += 256) {
            int r = i >> 4, c = i & 15;
            As[r][c] = A[(row0 + r) * K + k0 + c];
        }
        // load W tile 16x64
        #pragma unroll
        for (int i = threadIdx.x; i < 16 * 64; i += 256) {
            int r = i >> 6, c = i & 63;
            Bs[r][c] = W[(k0 + r) * N + col0 + c];
        }
        __syncthreads();

        #pragma unroll
        for (int kk = 0; kk < 16; kk++) {
            float a[4], b[4];
            #pragma unroll
            for (int i = 0; i < 4; i++) a[i] = As[ty * 4 + i][kk];
            #pragma unroll
            for (int j = 0; j < 4; j++) b[j] = Bs[kk][tx * 4 + j];
            #pragma unroll
            for (int i = 0; i < 4; i++)
                #pragma unroll
                for (int j = 0; j < 4; j++)
                    acc[i][j] = fmaf(a[i], b[j], acc[i][j]);
        }
        __syncthreads();
    }

    #pragma unroll
    for (int i = 0; i < 4; i++)
        #pragma unroll
        for (int j = 0; j < 4; j++)
            C[(row0 + ty * 4 + i) * N + col0 + tx * 4 + j] = acc[i][j];
}

// ---------------- RoPE + transpose to [B,H,S,DK] ----------------
// one thread per (b,s,h,i) pair, i in [0,32)
__global__ void rope_transpose_kernel(const int* __restrict__ pos,
                                      const float* __restrict__ cosT,
                                      const float* __restrict__ sinT)
{
    int idx = blockIdx.x * blockDim.x + threadIdx.x;
    // total = B*S*H*32 = 2097152
    int i = idx & 31;
    int h = (idx >> 5) & (HH - 1);
    int s = (idx >> 9) & (SS - 1);
    int b = idx >> 20;
    if (b >= BB) return;

    int p = pos[s];
    float c  = cosT[p * 32 + i];
    float sn = sinT[p * 32 + i];

    int src = (b * SS + s) * DD + h * DK + 2 * i;
    int dst = ((b * HH + h) * SS + s) * DK + 2 * i;

    float qe = g_Qraw[src], qo = g_Qraw[src + 1];
    g_Qh[dst]     = c * qe - sn * qo;
    g_Qh[dst + 1] = sn * qe + c * qo;

    float ke = g_Kraw[src], ko = g_Kraw[src + 1];
    g_Kh[dst]     = c * ke - sn * ko;
    g_Kh[dst + 1] = sn * ke + c * ko;

    g_Vh[dst]     = g_Vraw[src];
    g_Vh[dst + 1] = g_Vraw[src + 1];
}

// ---------------- causal attention ----------------
// grid: (S/8, B*H), block 256 = 8 warps; warp w handles query blockIdx.x*8 + w.
// Online softmax over key tiles of 32 shared by the block via smem.
__global__ void attn_kernel()
{
    __shared__ float qs[8][64];
    __shared__ float Ks[32][65];
    __shared__ float Vs[32][65];
    __shared__ float ps[8][32];

    int bh = blockIdx.y;               // b*H + h
    int b = bh >> 4, h = bh & 15;
    long base = (long)bh * SS * DK;

    int warp = threadIdx.x >> 5;
    int lane = threadIdx.x & 31;
    int q_idx = blockIdx.x * 8 + warp;

    // load 8 query rows
    for (int i = threadIdx.x; i < 8 * 64; i += 256) {
        int r = i >> 6, c = i & 63;
        qs[r][c] = g_Qh[base + (long)(blockIdx.x * 8 + r) * DK + c];
    }

    float m = -1e30f, l = 0.0f, o0 = 0.0f, o1 = 0.0f;

    int kmax = blockIdx.x * 8 + 7;
    int ntiles = (kmax >> 5) + 1;

    for (int t = 0; t < ntiles; t++) {
        __syncthreads();
        for (int i = threadIdx.x; i < 32 * 64; i += 256) {
            int r = i >> 6, c = i & 63;
            Ks[r][c] = g_Kh[base + (long)(t * 32 + r) * DK + c];
            Vs[r][c] = g_Vh[base + (long)(t * 32 + r) * DK + c];
        }
        __syncthreads();

        int kj = t * 32 + lane;
        bool valid = (kj <= q_idx);
        float s = 0.0f;
        if (valid) {
            #pragma unroll
            for (int d = 0; d < 64; d++)
                s = fmaf(qs[warp][d], Ks[lane][d], s);
            s *= 0.125f;   // 1/sqrt(64)
        } else {
            s = -1e30f;
        }

        // warp max
        float mt = s;
        #pragma unroll
        for (int off = 16; off; off >>= 1)
            mt = fmaxf(mt, __shfl_xor_sync(0xffffffffu, mt, off));
        float m_new = fmaxf(m, mt);

        float p = valid ? __expf(s - m_new) : 0.0f;
        float psum = p;
        #pragma unroll
        for (int off = 16; off; off >>= 1)
            psum += __shfl_xor_sync(0xffffffffu, psum, off);

        float alpha = __expf(m - m_new);
        l = l * alpha + psum;
        o0 *= alpha;
        o1 *= alpha;

        ps[warp][lane] = p;
        __syncwarp();

        #pragma unroll
        for (int j = 0; j < 32; j++) {
            float pj = ps[warp][j];
            o0 = fmaf(pj, Vs[j][lane],      o0);
            o1 = fmaf(pj, Vs[j][lane + 32], o1);
        }
        m = m_new;
    }

    float inv_l = 1.0f / l;
    long out_off = ((long)(b * SS + q_idx)) * DD + h * DK + lane;
    g_attn[out_off]      = o0 * inv_l;
    g_attn[out_off + 32] = o1 * inv_l;
}

// final projection reads g_attn
__global__ void gemm_out_kernel(const float* __restrict__ W, float* __restrict__ C)
{
    const int K = 1024, N = 1024;
    __shared__ float As[64][17];
    __shared__ float Bs[16][64];

    int tx = threadIdx.x & 15;
    int ty = threadIdx.x >> 4;
    int row0 = blockIdx.y * 64;
    int col0 = blockIdx.x * 64;

    float acc[4][4] = {};

    for (int k0 = 0; k0 < K; k0 += 16) {
        #pragma unroll
        for (int i = threadIdx.x; i < 64 * 16; i += 256) {
            int r = i >> 4, c = i & 15;
            As[r][c] = g_attn[(row0 + r) * K + k0 + c];
        }
        #pragma unroll
        for (int i = threadIdx.x; i < 16 * 64; i += 256) {
            int r = i >> 6, c = i & 63;
            Bs[r][c] = W[(k0 + r) * N + col0 + c];
        }
        __syncthreads();

        #pragma unroll
        for (int kk = 0; kk < 16; kk++) {
            float a[4], b[4];
            #pragma unroll
            for (int i = 0; i < 4; i++) a[i] = As[ty * 4 + i][kk];
            #pragma unroll
            for (int j = 0; j < 4; j++) b[j] = Bs[kk][tx * 4 + j];
            #pragma unroll
            for (int i = 0; i < 4; i++)
                #pragma unroll
                for (int j = 0; j < 4; j++)
                    acc[i][j] = fmaf(a[i], b[j], acc[i][j]);
        }
        __syncthreads();
    }

    #pragma unroll
    for (int i = 0; i < 4; i++)
        #pragma unroll
        for (int j = 0; j < 4; j++)
            C[(row0 + ty * 4 + i) * N + col0 + tx * 4 + j] = acc[i][j];
}

// ---------------- launch ----------------
extern "C" void kernel_launch(void* const* d_in, const int* in_sizes, int n_in,
                              void* d_out, int out_size)
{
    (void)in_sizes; (void)n_in; (void)out_size;
    const float* x    = (const float*)d_in[0];
    const int*   tpos = (const int*)  d_in[1];
    const float* W_Q  = (const float*)d_in[2];
    const float* W_K  = (const float*)d_in[3];
    const float* W_V  = (const float*)d_in[4];
    const float* W_O  = (const float*)d_in[5];
    const float* cosT = (const float*)d_in[6];
    const float* sinT = (const float*)d_in[7];
    float* out = (float*)d_out;

    void *pQraw, *pKraw, *pVraw;
    cudaGetSymbolAddress(&pQraw, g_Qraw);
    cudaGetSymbolAddress(&pKraw, g_Kraw);
    cudaGetSymbolAddress(&pVraw, g_Vraw);

    dim3 gblk(256);
    dim3 ggrid(1024 / 64, MM / 64);   // (16, 64)

    gemm_kernel<<<ggrid, gblk>>>(x, W_Q, (float*)pQraw);
    gemm_kernel<<<ggrid, gblk>>>(x, W_K, (float*)pKraw);
    gemm_kernel<<<ggrid, gblk>>>(x, W_V, (float*)pVraw);

    int rope_total = BB * SS * HH * 32;   // 2097152
    rope_transpose_kernel<<<rope_total / 256, 256>>>(tpos, cosT, sinT);

    dim3 agrid(SS / 8, BB * HH);      // (256, 32)
    attn_kernel<<<agrid, 256>>>();

    gemm_out_kernel<<<ggrid, gblk>>>(W_O, out);
}

// round 2
// speedup vs baseline: 1.5122x; 1.5122x over previous
#include <cuda_runtime.h>
#include <math.h>
#include <stdint.h>

#define BB 2
#define SS 2048
#define DD 1024
#define HH 16
#define DK 64
#define MM (BB*SS)   // 4096

// ---------------- scratch (static device memory; no allocations) ----------------
__device__ float g_Qraw[BB*SS*DD];
__device__ float g_Kraw[BB*SS*DD];
__device__ float g_Vraw[BB*SS*DD];
__device__ float g_Qh[BB*SS*DD];   // [B,H,S,DK]
__device__ float g_Kh[BB*SS*DD];
__device__ float g_Vh[BB*SS*DD];
__device__ float g_attn[BB*SS*DD]; // [B,S,D]

// ---------------- TF32 helpers ----------------
__device__ __forceinline__ float to_tf32(float x) {
    float y;
    asm("cvt.rna.tf32.f32 %0, %1;" : "=f"(y) : "f"(x));
    return y;
}

__device__ __forceinline__ void mma_tf32(float c[4],
                                         uint32_t a0, uint32_t a1, uint32_t a2, uint32_t a3,
                                         uint32_t b0, uint32_t b1)
{
    asm volatile("mma.sync.aligned.m16n8k8.row.col.f32.tf32.tf32.f32 "
                 "{%0,%1,%2,%3}, {%4,%5,%6,%7}, {%8,%9}, {%0,%1,%2,%3};"
                 : "+f"(c[0]), "+f"(c[1]), "+f"(c[2]), "+f"(c[3])
                 : "r"(a0), "r"(a1), "r"(a2), "r"(a3), "r"(b0), "r"(b1));
}

// ---------------- TF32 GEMM: C[4096,1024] = A[4096,1024] @ W[1024,1024] ----------------
// Block tile 128x128, 256 threads = 8 warps (2 M x 4 N), warp tile 64x32.
// mma m16n8k8 tf32, K-step 16.
#define AS_STRIDE 20    // 16 k + 4 pad  -> conflict-free A frag loads
#define BS_STRIDE 136   // 128 n + 8 pad -> conflict-free B frag loads

__global__ void __launch_bounds__(256, 2)
gemm_tf32_kernel(const float* __restrict__ A, const float* __restrict__ W,
                 float* __restrict__ C)
{
    const int K = 1024, N = 1024;
    __shared__ float As[128 * AS_STRIDE];   // [m][k], row-major k with pad
    __shared__ float Bs[16 * BS_STRIDE];    // [k][n], row-major n with pad

    const int tid  = threadIdx.x;
    const int warp = tid >> 5;
    const int lane = tid & 31;
    const int g = lane >> 2;     // group 0..7
    const int t = lane & 3;      // thread-in-group 0..3

    const int wm = warp & 1;     // 0..1 -> M offset
    const int wn = warp >> 1;    // 0..3 -> N offset
    const int warp_m = wm * 64;
    const int warp_n = wn * 32;

    const int row0 = blockIdx.y * 128;
    const int col0 = blockIdx.x * 128;

    // staging assignments
    const int a_row = tid >> 1;            // 0..127
    const int a_cg  = (tid & 1) * 8;       // 0 or 8
    const int b_row = tid >> 4;            // 0..15
    const int b_col = (tid & 15) * 8;      // 0..120

    float acc[4][4][4];                    // [fm][fn][reg]
    #pragma unroll
    for (int i = 0; i < 4; i++)
        #pragma unroll
        for (int j = 0; j < 4; j++)
            #pragma unroll
            for (int r = 0; r < 4; r++)
                acc[i][j][r] = 0.0f;

    for (int k0 = 0; k0 < K; k0 += 16) {
        // ---- stage A tile 128x16 (convert to tf32) ----
        {
            const float4* src = (const float4*)&A[(long)(row0 + a_row) * K + k0 + a_cg];
            float4 v0 = src[0];
            float4 v1 = src[1];
            float4 w0 = make_float4(to_tf32(v0.x), to_tf32(v0.y), to_tf32(v0.z), to_tf32(v0.w));
            float4 w1 = make_float4(to_tf32(v1.x), to_tf32(v1.y), to_tf32(v1.z), to_tf32(v1.w));
            float4* dst = (float4*)&As[a_row * AS_STRIDE + a_cg];
            dst[0] = w0;
            dst[1] = w1;
        }
        // ---- stage B tile 16x128 (convert to tf32) ----
        {
            const float4* src = (const float4*)&W[(long)(k0 + b_row) * N + col0 + b_col];
            float4 v0 = src[0];
            float4 v1 = src[1];
            float4 w0 = make_float4(to_tf32(v0.x), to_tf32(v0.y), to_tf32(v0.z), to_tf32(v0.w));
            float4 w1 = make_float4(to_tf32(v1.x), to_tf32(v1.y), to_tf32(v1.z), to_tf32(v1.w));
            float4* dst = (float4*)&Bs[b_row * BS_STRIDE + b_col];
            dst[0] = w0;
            dst[1] = w1;
        }
        __syncthreads();

        #pragma unroll
        for (int chunk = 0; chunk < 2; chunk++) {
            const int kc = chunk * 8;

            uint32_t af[4][4];   // [fm][reg]
            #pragma unroll
            for (int fm = 0; fm < 4; fm++) {
                int mrow = warp_m + fm * 16 + g;
                const float* pa = &As[mrow * AS_STRIDE + kc + t];
                af[fm][0] = __float_as_uint(pa[0]);
                af[fm][1] = __float_as_uint(pa[8 * AS_STRIDE]);
                af[fm][2] = __float_as_uint(pa[4]);
                af[fm][3] = __float_as_uint(pa[8 * AS_STRIDE + 4]);
            }
            uint32_t bf[4][2];   // [fn][reg]
            #pragma unroll
            for (int fn = 0; fn < 4; fn++) {
                const float* pb = &Bs[(kc + t) * BS_STRIDE + warp_n + fn * 8 + g];
                bf[fn][0] = __float_as_uint(pb[0]);
                bf[fn][1] = __float_as_uint(pb[4 * BS_STRIDE]);
            }

            #pragma unroll
            for (int fm = 0; fm < 4; fm++)
                #pragma unroll
                for (int fn = 0; fn < 4; fn++)
                    mma_tf32(acc[fm][fn],
                             af[fm][0], af[fm][1], af[fm][2], af[fm][3],
                             bf[fn][0], bf[fn][1]);
        }
        __syncthreads();
    }

    // ---- epilogue ----
    #pragma unroll
    for (int fm = 0; fm < 4; fm++) {
        #pragma unroll
        for (int fn = 0; fn < 4; fn++) {
            int r0 = row0 + warp_m + fm * 16 + g;
            int c0 = col0 + warp_n + fn * 8 + 2 * t;
            float2* p0 = (float2*)&C[(long)r0 * N + c0];
            *p0 = make_float2(acc[fm][fn][0], acc[fm][fn][1]);
            float2* p1 = (float2*)&C[(long)(r0 + 8) * N + c0];
            *p1 = make_float2(acc[fm][fn][2], acc[fm][fn][3]);
        }
    }
}

// ---------------- RoPE + transpose to [B,H,S,DK] ----------------
__global__ void rope_transpose_kernel(const int* __restrict__ pos,
                                      const float* __restrict__ cosT,
                                      const float* __restrict__ sinT)
{
    int idx = blockIdx.x * blockDim.x + threadIdx.x;
    int i = idx & 31;
    int h = (idx >> 5) & (HH - 1);
    int s = (idx >> 9) & (SS - 1);
    int b = idx >> 20;
    if (b >= BB) return;

    int p = pos[s];
    float c  = cosT[p * 32 + i];
    float sn = sinT[p * 32 + i];

    int src = (b * SS + s) * DD + h * DK + 2 * i;
    int dst = ((b * HH + h) * SS + s) * DK + 2 * i;

    float qe = g_Qraw[src], qo = g_Qraw[src + 1];
    g_Qh[dst]     = c * qe - sn * qo;
    g_Qh[dst + 1] = sn * qe + c * qo;

    float ke = g_Kraw[src], ko = g_Kraw[src + 1];
    g_Kh[dst]     = c * ke - sn * ko;
    g_Kh[dst + 1] = sn * ke + c * ko;

    g_Vh[dst]     = g_Vraw[src];
    g_Vh[dst + 1] = g_Vraw[src + 1];
}

// ---------------- causal attention (unchanged this round) ----------------
__global__ void attn_kernel()
{
    __shared__ float qs[8][64];
    __shared__ float Ks[32][65];
    __shared__ float Vs[32][65];
    __shared__ float ps[8][32];

    int bh = blockIdx.y;
    int b = bh >> 4, h = bh & 15;
    long base = (long)bh * SS * DK;

    int warp = threadIdx.x >> 5;
    int lane = threadIdx.x & 31;
    int q_idx = blockIdx.x * 8 + warp;

    for (int i = threadIdx.x; i < 8 * 64; i += 256) {
        int r = i >> 6, c = i & 63;
        qs[r][c] = g_Qh[base + (long)(blockIdx.x * 8 + r) * DK + c];
    }

    float m = -1e30f, l = 0.0f, o0 = 0.0f, o1 = 0.0f;

    int kmax = blockIdx.x * 8 + 7;
    int ntiles = (kmax >> 5) + 1;

    for (int t = 0; t < ntiles; t++) {
        __syncthreads();
        for (int i = threadIdx.x; i < 32 * 64; i += 256) {
            int r = i >> 6, c = i & 63;
            Ks[r][c] = g_Kh[base + (long)(t * 32 + r) * DK + c];
            Vs[r][c] = g_Vh[base + (long)(t * 32 + r) * DK + c];
        }
        __syncthreads();

        int kj = t * 32 + lane;
        bool valid = (kj <= q_idx);
        float s = 0.0f;
        if (valid) {
            #pragma unroll
            for (int d = 0; d < 64; d++)
                s = fmaf(qs[warp][d], Ks[lane][d], s);
            s *= 0.125f;
        } else {
            s = -1e30f;
        }

        float mt = s;
        #pragma unroll
        for (int off = 16; off; off >>= 1)
            mt = fmaxf(mt, __shfl_xor_sync(0xffffffffu, mt, off));
        float m_new = fmaxf(m, mt);

        float p = valid ? __expf(s - m_new) : 0.0f;
        float psum = p;
        #pragma unroll
        for (int off = 16; off; off >>= 1)
            psum += __shfl_xor_sync(0xffffffffu, psum, off);

        float alpha = __expf(m - m_new);
        l = l * alpha + psum;
        o0 *= alpha;
        o1 *= alpha;

        ps[warp][lane] = p;
        __syncwarp();

        #pragma unroll
        for (int j = 0; j < 32; j++) {
            float pj = ps[warp][j];
            o0 = fmaf(pj, Vs[j][lane],      o0);
            o1 = fmaf(pj, Vs[j][lane + 32], o1);
        }
        m = m_new;
    }

    float inv_l = 1.0f / l;
    long out_off = ((long)(b * SS + q_idx)) * DD + h * DK + lane;
    g_attn[out_off]      = o0 * inv_l;
    g_attn[out_off + 32] = o1 * inv_l;
}

// ---------------- launch ----------------
extern "C" void kernel_launch(void* const* d_in, const int* in_sizes, int n_in,
                              void* d_out, int out_size)
{
    (void)in_sizes; (void)n_in; (void)out_size;
    const float* x    = (const float*)d_in[0];
    const int*   tpos = (const int*)  d_in[1];
    const float* W_Q  = (const float*)d_in[2];
    const float* W_K  = (const float*)d_in[3];
    const float* W_V  = (const float*)d_in[4];
    const float* W_O  = (const float*)d_in[5];
    const float* cosT = (const float*)d_in[6];
    const float* sinT = (const float*)d_in[7];
    float* out = (float*)d_out;

    void *pQraw, *pKraw, *pVraw, *pAttn;
    cudaGetSymbolAddress(&pQraw, g_Qraw);
    cudaGetSymbolAddress(&pKraw, g_Kraw);
    cudaGetSymbolAddress(&pVraw, g_Vraw);
    cudaGetSymbolAddress(&pAttn, g_attn);

    dim3 gblk(256);
    dim3 ggrid(1024 / 128, MM / 128);   // (8, 32)

    gemm_tf32_kernel<<<ggrid, gblk>>>(x, W_Q, (float*)pQraw);
    gemm_tf32_kernel<<<ggrid, gblk>>>(x, W_K, (float*)pKraw);
    gemm_tf32_kernel<<<ggrid, gblk>>>(x, W_V, (float*)pVraw);

    int rope_total = BB * SS * HH * 32;
    rope_transpose_kernel<<<rope_total / 256, 256>>>(tpos, cosT, sinT);

    dim3 agrid(SS / 8, BB * HH);
    attn_kernel<<<agrid, 256>>>();

    gemm_tf32_kernel<<<ggrid, gblk>>>((const float*)pAttn, W_O, out);
}

// round 3
// speedup vs baseline: 3.4465x; 2.2791x over previous
#include <cuda_runtime.h>
#include <math.h>
#include <stdint.h>

#define BB 2
#define SS 2048
#define DD 1024
#define HH 16
#define DK 64
#define MM (BB*SS)   // 4096

// ---------------- scratch (static device memory; no allocations) ----------------
__device__ float g_Qraw[BB*SS*DD];
__device__ float g_Kraw[BB*SS*DD];
__device__ float g_Vraw[BB*SS*DD];
__device__ float g_Qh[BB*SS*DD];   // [B,H,S,DK]
__device__ float g_Kh[BB*SS*DD];
__device__ float g_Vh[BB*SS*DD];
__device__ float g_attn[BB*SS*DD]; // [B,S,D]

// ---------------- TF32 helpers ----------------
__device__ __forceinline__ float to_tf32(float x) {
    float y;
    asm("cvt.rna.tf32.f32 %0, %1;" : "=f"(y) : "f"(x));
    return y;
}

__device__ __forceinline__ void mma_tf32(float c[4],
                                         uint32_t a0, uint32_t a1, uint32_t a2, uint32_t a3,
                                         uint32_t b0, uint32_t b1)
{
    asm volatile("mma.sync.aligned.m16n8k8.row.col.f32.tf32.tf32.f32 "
                 "{%0,%1,%2,%3}, {%4,%5,%6,%7}, {%8,%9}, {%0,%1,%2,%3};"
                 : "+f"(c[0]), "+f"(c[1]), "+f"(c[2]), "+f"(c[3])
                 : "r"(a0), "r"(a1), "r"(a2), "r"(a3), "r"(b0), "r"(b1));
}

// ---------------- TF32 GEMM: C[4096,1024] = A[4096,1024] @ W[1024,1024] ----------------
#define AS_STRIDE 20
#define BS_STRIDE 136

__global__ void __launch_bounds__(256, 2)
gemm_tf32_kernel(const float* __restrict__ A, const float* __restrict__ W,
                 float* __restrict__ C)
{
    const int K = 1024, N = 1024;
    __shared__ float As[128 * AS_STRIDE];
    __shared__ float Bs[16 * BS_STRIDE];

    const int tid  = threadIdx.x;
    const int warp = tid >> 5;
    const int lane = tid & 31;
    const int g = lane >> 2;
    const int t = lane & 3;

    const int wm = warp & 1;
    const int wn = warp >> 1;
    const int warp_m = wm * 64;
    const int warp_n = wn * 32;

    const int row0 = blockIdx.y * 128;
    const int col0 = blockIdx.x * 128;

    const int a_row = tid >> 1;
    const int a_cg  = (tid & 1) * 8;
    const int b_row = tid >> 4;
    const int b_col = (tid & 15) * 8;

    float acc[4][4][4];
    #pragma unroll
    for (int i = 0; i < 4; i++)
        #pragma unroll
        for (int j = 0; j < 4; j++)
            #pragma unroll
            for (int r = 0; r < 4; r++)
                acc[i][j][r] = 0.0f;

    for (int k0 = 0; k0 < K; k0 += 16) {
        {
            const float4* src = (const float4*)&A[(long)(row0 + a_row) * K + k0 + a_cg];
            float4 v0 = src[0];
            float4 v1 = src[1];
            float4 w0 = make_float4(to_tf32(v0.x), to_tf32(v0.y), to_tf32(v0.z), to_tf32(v0.w));
            float4 w1 = make_float4(to_tf32(v1.x), to_tf32(v1.y), to_tf32(v1.z), to_tf32(v1.w));
            float4* dst = (float4*)&As[a_row * AS_STRIDE + a_cg];
            dst[0] = w0;
            dst[1] = w1;
        }
        {
            const float4* src = (const float4*)&W[(long)(k0 + b_row) * N + col0 + b_col];
            float4 v0 = src[0];
            float4 v1 = src[1];
            float4 w0 = make_float4(to_tf32(v0.x), to_tf32(v0.y), to_tf32(v0.z), to_tf32(v0.w));
            float4 w1 = make_float4(to_tf32(v1.x), to_tf32(v1.y), to_tf32(v1.z), to_tf32(v1.w));
            float4* dst = (float4*)&Bs[b_row * BS_STRIDE + b_col];
            dst[0] = w0;
            dst[1] = w1;
        }
        __syncthreads();

        #pragma unroll
        for (int chunk = 0; chunk < 2; chunk++) {
            const int kc = chunk * 8;

            uint32_t af[4][4];
            #pragma unroll
            for (int fm = 0; fm < 4; fm++) {
                int mrow = warp_m + fm * 16 + g;
                const float* pa = &As[mrow * AS_STRIDE + kc + t];
                af[fm][0] = __float_as_uint(pa[0]);
                af[fm][1] = __float_as_uint(pa[8 * AS_STRIDE]);
                af[fm][2] = __float_as_uint(pa[4]);
                af[fm][3] = __float_as_uint(pa[8 * AS_STRIDE + 4]);
            }
            uint32_t bf[4][2];
            #pragma unroll
            for (int fn = 0; fn < 4; fn++) {
                const float* pb = &Bs[(kc + t) * BS_STRIDE + warp_n + fn * 8 + g];
                bf[fn][0] = __float_as_uint(pb[0]);
                bf[fn][1] = __float_as_uint(pb[4 * BS_STRIDE]);
            }

            #pragma unroll
            for (int fm = 0; fm < 4; fm++)
                #pragma unroll
                for (int fn = 0; fn < 4; fn++)
                    mma_tf32(acc[fm][fn],
                             af[fm][0], af[fm][1], af[fm][2], af[fm][3],
                             bf[fn][0], bf[fn][1]);
        }
        __syncthreads();
    }

    #pragma unroll
    for (int fm = 0; fm < 4; fm++) {
        #pragma unroll
        for (int fn = 0; fn < 4; fn++) {
            int r0 = row0 + warp_m + fm * 16 + g;
            int c0 = col0 + warp_n + fn * 8 + 2 * t;
            float2* p0 = (float2*)&C[(long)r0 * N + c0];
            *p0 = make_float2(acc[fm][fn][0], acc[fm][fn][1]);
            float2* p1 = (float2*)&C[(long)(r0 + 8) * N + c0];
            *p1 = make_float2(acc[fm][fn][2], acc[fm][fn][3]);
        }
    }
}

// ---------------- RoPE + transpose to [B,H,S,DK] ----------------
__global__ void rope_transpose_kernel(const int* __restrict__ pos,
                                      const float* __restrict__ cosT,
                                      const float* __restrict__ sinT)
{
    int idx = blockIdx.x * blockDim.x + threadIdx.x;
    int i = idx & 31;
    int h = (idx >> 5) & (HH - 1);
    int s = (idx >> 9) & (SS - 1);
    int b = idx >> 20;
    if (b >= BB) return;

    int p = pos[s];
    float c  = cosT[p * 32 + i];
    float sn = sinT[p * 32 + i];

    int src = (b * SS + s) * DD + h * DK + 2 * i;
    int dst = ((b * HH + h) * SS + s) * DK + 2 * i;

    float qe = g_Qraw[src], qo = g_Qraw[src + 1];
    g_Qh[dst]     = c * qe - sn * qo;
    g_Qh[dst + 1] = sn * qe + c * qo;

    float ke = g_Kraw[src], ko = g_Kraw[src + 1];
    g_Kh[dst]     = c * ke - sn * ko;
    g_Kh[dst + 1] = sn * ke + c * ko;

    g_Vh[dst]     = g_Vraw[src];
    g_Vh[dst + 1] = g_Vraw[src + 1];
}

// ---------------- flash attention (3xTF32 mma, causal) ----------------
// Br=64 (4 warps x 16 rows), Bc=32. Dynamic smem: hi/lo planes.
#define KV_STRIDE 72   // bank = 8n + k  -> conflict-free B-frag loads
#define P_STRIDE  36   // bank = 4r + k  -> conflict-free A-frag loads

// float offsets into dynamic smem
#define SQH 0
#define SQL (SQH + 64*KV_STRIDE)
#define SKH (SQL + 64*KV_STRIDE)
#define SKL (SKH + 32*KV_STRIDE)
#define SVH (SKL + 32*KV_STRIDE)
#define SVL (SVH + 32*KV_STRIDE)
#define SPH (SVL + 32*KV_STRIDE)
#define SPL (SPH + 64*P_STRIDE)
#define SMEM_FLOATS (SPL + 64*P_STRIDE)   // 23040 floats = 92160 B

__global__ void __launch_bounds__(128)
flash_attn_kernel()
{
    extern __shared__ float sm[];
    float* sQh = sm + SQH;
    float* sQl = sm + SQL;
    float* sKh = sm + SKH;
    float* sKl = sm + SKL;
    float* sVh = sm + SVH;
    float* sVl = sm + SVL;
    float* sPh = sm + SPH;
    float* sPl = sm + SPL;

    const int tid  = threadIdx.x;
    const int warp = tid >> 5;
    const int lane = tid & 31;
    const int g = lane >> 2;
    const int t = lane & 3;

    const int bx = gridDim.x - 1 - blockIdx.x;   // heavy tiles first
    const int bh = blockIdx.y;
    const int b = bh >> 4, h = bh & 15;
    const long base = (long)bh * SS * DK;
    const int q0 = bx * 64;

    // ---- stage Q (hi/lo split), once ----
    {
        const float* Qg = g_Qh + base + (long)q0 * DK;
        int row = tid >> 1;
        int d0 = (tid & 1) * 32;
        #pragma unroll
        for (int i = 0; i < 8; i++) {
            float4 v = *(const float4*)(Qg + row * 64 + d0 + i * 4);
            float4 hi = make_float4(to_tf32(v.x), to_tf32(v.y), to_tf32(v.z), to_tf32(v.w));
            float4 lo = make_float4(to_tf32(v.x - hi.x), to_tf32(v.y - hi.y),
                                    to_tf32(v.z - hi.z), to_tf32(v.w - hi.w));
            *(float4*)(sQh + row * KV_STRIDE + d0 + i * 4) = hi;
            *(float4*)(sQl + row * KV_STRIDE + d0 + i * 4) = lo;
        }
    }

    // per-thread softmax state: rows r0 = q0+16*warp+g  and  r0+8
    float m0 = -1e30f, m1 = -1e30f, l0 = 0.0f, l1 = 0.0f;
    float O[8][4];
    #pragma unroll
    for (int fn = 0; fn < 8; fn++)
        #pragma unroll
        for (int r = 0; r < 4; r++)
            O[fn][r] = 0.0f;

    const int pr0 = warp * 16 + g;       // local row (warp-owned)
    const int r0g = q0 + pr0;            // global rows
    const int r1g = r0g + 8;
    const int ntiles = 2 * bx + 2;

    // K/V staging assignment
    const int s_key = tid >> 2;          // 0..31
    const int s_d0  = (tid & 3) * 16;

    for (int kt = 0; kt < ntiles; kt++) {
        __syncthreads();   // prior-tile K/V consumers done (also covers Q staging on kt=0)

        // ---- stage K, V tile (hi/lo) ----
        {
            const int key0 = kt * 32;
            const float* Kg = g_Kh + base + (long)(key0 + s_key) * DK + s_d0;
            const float* Vg = g_Vh + base + (long)(key0 + s_key) * DK + s_d0;
            #pragma unroll
            for (int i = 0; i < 4; i++) {
                float4 v = *(const float4*)(Kg + i * 4);
                float4 hi = make_float4(to_tf32(v.x), to_tf32(v.y), to_tf32(v.z), to_tf32(v.w));
                float4 lo = make_float4(to_tf32(v.x - hi.x), to_tf32(v.y - hi.y),
                                        to_tf32(v.z - hi.z), to_tf32(v.w - hi.w));
                *(float4*)(sKh + s_key * KV_STRIDE + s_d0 + i * 4) = hi;
                *(float4*)(sKl + s_key * KV_STRIDE + s_d0 + i * 4) = lo;
            }
            #pragma unroll
            for (int i = 0; i < 4; i++) {
                float4 v = *(const float4*)(Vg + i * 4);
                float4 hi = make_float4(to_tf32(v.x), to_tf32(v.y), to_tf32(v.z), to_tf32(v.w));
                float4 lo = make_float4(to_tf32(v.x - hi.x), to_tf32(v.y - hi.y),
                                        to_tf32(v.z - hi.z), to_tf32(v.w - hi.w));
                *(float4*)(sVh + s_key * KV_STRIDE + s_d0 + i * 4) = hi;
                *(float4*)(sVl + s_key * KV_STRIDE + s_d0 + i * 4) = lo;
            }
        }
        __syncthreads();

        // ---- S = Q K^T (3xTF32) ----
        float S[4][4];
        #pragma unroll
        for (int fn = 0; fn < 4; fn++)
            #pragma unroll
            for (int r = 0; r < 4; r++)
                S[fn][r] = 0.0f;

        #pragma unroll
        for (int kc = 0; kc < 8; kc++) {
            const int k8 = kc * 8;
            const float* qh = sQh + pr0 * KV_STRIDE + k8 + t;
            const float* ql = sQl + pr0 * KV_STRIDE + k8 + t;
            uint32_t ah0 = __float_as_uint(qh[0]);
            uint32_t ah1 = __float_as_uint(qh[8 * KV_STRIDE]);
            uint32_t ah2 = __float_as_uint(qh[4]);
            uint32_t ah3 = __float_as_uint(qh[8 * KV_STRIDE + 4]);
            uint32_t al0 = __float_as_uint(ql[0]);
            uint32_t al1 = __float_as_uint(ql[8 * KV_STRIDE]);
            uint32_t al2 = __float_as_uint(ql[4]);
            uint32_t al3 = __float_as_uint(ql[8 * KV_STRIDE + 4]);

            #pragma unroll
            for (int fn = 0; fn < 4; fn++) {
                const int n = fn * 8 + g;
                const float* kh = sKh + n * KV_STRIDE + k8 + t;
                const float* kl = sKl + n * KV_STRIDE + k8 + t;
                uint32_t bh0 = __float_as_uint(kh[0]);
                uint32_t bh1 = __float_as_uint(kh[4]);
                uint32_t bl0 = __float_as_uint(kl[0]);
                uint32_t bl1 = __float_as_uint(kl[4]);
                mma_tf32(S[fn], ah0, ah1, ah2, ah3, bh0, bh1);
                mma_tf32(S[fn], ah0, ah1, ah2, ah3, bl0, bl1);
                mma_tf32(S[fn], al0, al1, al2, al3, bh0, bh1);
            }
        }

        // ---- scale + causal mask ----
        const int key0 = kt * 32;
        const bool edge = (kt >= 2 * bx);   // only last two tiles touch the diagonal
        #pragma unroll
        for (int fn = 0; fn < 4; fn++) {
            #pragma unroll
            for (int r = 0; r < 4; r++)
                S[fn][r] *= 0.125f;
            if (edge) {
                const int cg = key0 + fn * 8 + 2 * t;
                if (cg     > r0g) S[fn][0] = -1e30f;
                if (cg + 1 > r0g) S[fn][1] = -1e30f;
                if (cg     > r1g) S[fn][2] = -1e30f;
                if (cg + 1 > r1g) S[fn][3] = -1e30f;
            }
        }

        // ---- online softmax ----
        float mt0 = fmaxf(fmaxf(S[0][0], S[0][1]), fmaxf(S[1][0], S[1][1]));
        mt0 = fmaxf(mt0, fmaxf(fmaxf(S[2][0], S[2][1]), fmaxf(S[3][0], S[3][1])));
        float mt1 = fmaxf(fmaxf(S[0][2], S[0][3]), fmaxf(S[1][2], S[1][3]));
        mt1 = fmaxf(mt1, fmaxf(fmaxf(S[2][2], S[2][3]), fmaxf(S[3][2], S[3][3])));
        mt0 = fmaxf(mt0, __shfl_xor_sync(0xffffffffu, mt0, 1));
        mt0 = fmaxf(mt0, __shfl_xor_sync(0xffffffffu, mt0, 2));
        mt1 = fmaxf(mt1, __shfl_xor_sync(0xffffffffu, mt1, 1));
        mt1 = fmaxf(mt1, __shfl_xor_sync(0xffffffffu, mt1, 2));

        const float m0n = fmaxf(m0, mt0);
        const float m1n = fmaxf(m1, mt1);
        const float a0 = __expf(m0 - m0n);
        const float a1 = __expf(m1 - m1n);

        float P[4][4];
        float ps0 = 0.0f, ps1 = 0.0f;
        #pragma unroll
        for (int fn = 0; fn < 4; fn++) {
            P[fn][0] = __expf(S[fn][0] - m0n);
            P[fn][1] = __expf(S[fn][1] - m0n);
            P[fn][2] = __expf(S[fn][2] - m1n);
            P[fn][3] = __expf(S[fn][3] - m1n);
            ps0 += P[fn][0] + P[fn][1];
            ps1 += P[fn][2] + P[fn][3];
        }
        ps0 += __shfl_xor_sync(0xffffffffu, ps0, 1);
        ps0 += __shfl_xor_sync(0xffffffffu, ps0, 2);
        ps1 += __shfl_xor_sync(0xffffffffu, ps1, 1);
        ps1 += __shfl_xor_sync(0xffffffffu, ps1, 2);

        l0 = l0 * a0 + ps0;
        l1 = l1 * a1 + ps1;
        m0 = m0n;
        m1 = m1n;

        #pragma unroll
        for (int fn = 0; fn < 8; fn++) {
            O[fn][0] *= a0;
            O[fn][1] *= a0;
            O[fn][2] *= a1;
            O[fn][3] *= a1;
        }

        // ---- write P hi/lo to smem (warp-local rows) ----
        #pragma unroll
        for (int fn = 0; fn < 4; fn++) {
            const int col = fn * 8 + 2 * t;
            float h0 = to_tf32(P[fn][0]), h1 = to_tf32(P[fn][1]);
            float h2 = to_tf32(P[fn][2]), h3 = to_tf32(P[fn][3]);
            *(float2*)(sPh + pr0 * P_STRIDE + col)       = make_float2(h0, h1);
            *(float2*)(sPh + (pr0 + 8) * P_STRIDE + col) = make_float2(h2, h3);
            *(float2*)(sPl + pr0 * P_STRIDE + col)       =
                make_float2(to_tf32(P[fn][0] - h0), to_tf32(P[fn][1] - h1));
            *(float2*)(sPl + (pr0 + 8) * P_STRIDE + col) =
                make_float2(to_tf32(P[fn][2] - h2), to_tf32(P[fn][3] - h3));
        }
        __syncwarp();

        // ---- O += P V (3xTF32) ----
        #pragma unroll
        for (int kc = 0; kc < 4; kc++) {
            const int k8 = kc * 8;
            const float* ph = sPh + pr0 * P_STRIDE + k8 + t;
            const float* pl = sPl + pr0 * P_STRIDE + k8 + t;
            uint32_t ah0 = __float_as_uint(ph[0]);
            uint32_t ah1 = __float_as_uint(ph[8 * P_STRIDE]);
            uint32_t ah2 = __float_as_uint(ph[4]);
            uint32_t ah3 = __float_as_uint(ph[8 * P_STRIDE + 4]);
            uint32_t al0 = __float_as_uint(pl[0]);
            uint32_t al1 = __float_as_uint(pl[8 * P_STRIDE]);
            uint32_t al2 = __float_as_uint(pl[4]);
            uint32_t al3 = __float_as_uint(pl[8 * P_STRIDE + 4]);

            #pragma unroll
            for (int fn = 0; fn < 8; fn++) {
                const int n = fn * 8 + g;
                const float* vh = sVh + (k8 + t) * KV_STRIDE + n;
                const float* vl = sVl + (k8 + t) * KV_STRIDE + n;
                uint32_t bh0 = __float_as_uint(vh[0]);
                uint32_t bh1 = __float_as_uint(vh[4 * KV_STRIDE]);
                uint32_t bl0 = __float_as_uint(vl[0]);
                uint32_t bl1 = __float_as_uint(vl[4 * KV_STRIDE]);
                mma_tf32(O[fn], ah0, ah1, ah2, ah3, bh0, bh1);
                mma_tf32(O[fn], ah0, ah1, ah2, ah3, bl0, bl1);
                mma_tf32(O[fn], al0, al1, al2, al3, bh0, bh1);
            }
        }
    }

    // ---- epilogue: normalize + write [B,S,H*DK] ----
    const float il0 = 1.0f / l0;
    const float il1 = 1.0f / l1;
    const long o0 = ((long)(b * SS + r0g)) * DD + h * DK;
    const long o1 = ((long)(b * SS + r1g)) * DD + h * DK;
    #pragma unroll
    for (int fn = 0; fn < 8; fn++) {
        const int col = fn * 8 + 2 * t;
        *(float2*)(g_attn + o0 + col) = make_float2(O[fn][0] * il0, O[fn][1] * il0);
        *(float2*)(g_attn + o1 + col) = make_float2(O[fn][2] * il1, O[fn][3] * il1);
    }
}

// ---------------- launch ----------------
extern "C" void kernel_launch(void* const* d_in, const int* in_sizes, int n_in,
                              void* d_out, int out_size)
{
    (void)in_sizes; (void)n_in; (void)out_size;
    const float* x    = (const float*)d_in[0];
    const int*   tpos = (const int*)  d_in[1];
    const float* W_Q  = (const float*)d_in[2];
    const float* W_K  = (const float*)d_in[3];
    const float* W_V  = (const float*)d_in[4];
    const float* W_O  = (const float*)d_in[5];
    const float* cosT = (const float*)d_in[6];
    const float* sinT = (const float*)d_in[7];
    float* out = (float*)d_out;

    void *pQraw, *pKraw, *pVraw, *pAttn;
    cudaGetSymbolAddress(&pQraw, g_Qraw);
    cudaGetSymbolAddress(&pKraw, g_Kraw);
    cudaGetSymbolAddress(&pVraw, g_Vraw);
    cudaGetSymbolAddress(&pAttn, g_attn);

    static int attn_smem_set = 0;
    if (!attn_smem_set) {
        cudaFuncSetAttribute(flash_attn_kernel,
                             cudaFuncAttributeMaxDynamicSharedMemorySize,
                             SMEM_FLOATS * sizeof(float));
        attn_smem_set = 1;
    }

    dim3 gblk(256);
    dim3 ggrid(1024 / 128, MM / 128);   // (8, 32)

    gemm_tf32_kernel<<<ggrid, gblk>>>(x, W_Q, (float*)pQraw);
    gemm_tf32_kernel<<<ggrid, gblk>>>(x, W_K, (float*)pKraw);
    gemm_tf32_kernel<<<ggrid, gblk>>>(x, W_V, (float*)pVraw);

    int rope_total = BB * SS * HH * 32;
    rope_transpose_kernel<<<rope_total / 256, 256>>>(tpos, cosT, sinT);

    dim3 agrid(SS / 64, BB * HH);        // (32, 32)
    flash_attn_kernel<<<agrid, 128, SMEM_FLOATS * sizeof(float)>>>();

    gemm_tf32_kernel<<<ggrid, gblk>>>((const float*)pAttn, W_O, out);
}

// round 4
// speedup vs baseline: 3.5241x; 1.0225x over previous
#include <cuda_runtime.h>
#include <math.h>
#include <stdint.h>

#define BB 2
#define SS 2048
#define DD 1024
#define HH 16
#define DK 64
#define MM (BB*SS)   // 4096

// ---------------- scratch (static device memory; no allocations) ----------------
__device__ float g_Qraw[BB*SS*DD];
__device__ float g_Kraw[BB*SS*DD];
__device__ float g_Vraw[BB*SS*DD];
__device__ float g_Qh[BB*SS*DD];   // [B,H,S,DK]
__device__ float g_Kh[BB*SS*DD];
__device__ float g_Vh[BB*SS*DD];
__device__ float g_attn[BB*SS*DD]; // [B,S,D]

// ---------------- TF32 helpers ----------------
__device__ __forceinline__ float to_tf32(float x) {
    float y;
    asm("cvt.rna.tf32.f32 %0, %1;" : "=f"(y) : "f"(x));
    return y;
}

__device__ __forceinline__ void mma_tf32(float c[4],
                                         uint32_t a0, uint32_t a1, uint32_t a2, uint32_t a3,
                                         uint32_t b0, uint32_t b1)
{
    asm volatile("mma.sync.aligned.m16n8k8.row.col.f32.tf32.tf32.f32 "
                 "{%0,%1,%2,%3}, {%4,%5,%6,%7}, {%8,%9}, {%0,%1,%2,%3};"
                 : "+f"(c[0]), "+f"(c[1]), "+f"(c[2]), "+f"(c[3])
                 : "r"(a0), "r"(a1), "r"(a2), "r"(a3), "r"(b0), "r"(b1));
}

__device__ __forceinline__ void cp_async16(uint32_t saddr, const void* gptr) {
    asm volatile("cp.async.cg.shared.global [%0], [%1], 16;"
                 :: "r"(saddr), "l"(gptr));
}
__device__ __forceinline__ void cp_commit() {
    asm volatile("cp.async.commit_group;");
}
template<int N>
__device__ __forceinline__ void cp_wait() {
    asm volatile("cp.async.wait_group %0;" :: "n"(N));
}

// ---------------- TF32 GEMM: C[4096,1024] = A[4096,1024] @ W[1024,1024] ----------------
#define AS_STRIDE 20
#define BS_STRIDE 136

__global__ void __launch_bounds__(256, 2)
gemm_tf32_kernel(const float* __restrict__ A, const float* __restrict__ W,
                 float* __restrict__ C)
{
    const int K = 1024, N = 1024;
    __shared__ float As[128 * AS_STRIDE];
    __shared__ float Bs[16 * BS_STRIDE];

    const int tid  = threadIdx.x;
    const int warp = tid >> 5;
    const int lane = tid & 31;
    const int g = lane >> 2;
    const int t = lane & 3;

    const int wm = warp & 1;
    const int wn = warp >> 1;
    const int warp_m = wm * 64;
    const int warp_n = wn * 32;

    const int row0 = blockIdx.y * 128;
    const int col0 = blockIdx.x * 128;

    const int a_row = tid >> 1;
    const int a_cg  = (tid & 1) * 8;
    const int b_row = tid >> 4;
    const int b_col = (tid & 15) * 8;

    float acc[4][4][4];
    #pragma unroll
    for (int i = 0; i < 4; i++)
        #pragma unroll
        for (int j = 0; j < 4; j++)
            #pragma unroll
            for (int r = 0; r < 4; r++)
                acc[i][j][r] = 0.0f;

    for (int k0 = 0; k0 < K; k0 += 16) {
        {
            const float4* src = (const float4*)&A[(long)(row0 + a_row) * K + k0 + a_cg];
            float4 v0 = src[0];
            float4 v1 = src[1];
            float4 w0 = make_float4(to_tf32(v0.x), to_tf32(v0.y), to_tf32(v0.z), to_tf32(v0.w));
            float4 w1 = make_float4(to_tf32(v1.x), to_tf32(v1.y), to_tf32(v1.z), to_tf32(v1.w));
            float4* dst = (float4*)&As[a_row * AS_STRIDE + a_cg];
            dst[0] = w0;
            dst[1] = w1;
        }
        {
            const float4* src = (const float4*)&W[(long)(k0 + b_row) * N + col0 + b_col];
            float4 v0 = src[0];
            float4 v1 = src[1];
            float4 w0 = make_float4(to_tf32(v0.x), to_tf32(v0.y), to_tf32(v0.z), to_tf32(v0.w));
            float4 w1 = make_float4(to_tf32(v1.x), to_tf32(v1.y), to_tf32(v1.z), to_tf32(v1.w));
            float4* dst = (float4*)&Bs[b_row * BS_STRIDE + b_col];
            dst[0] = w0;
            dst[1] = w1;
        }
        __syncthreads();

        #pragma unroll
        for (int chunk = 0; chunk < 2; chunk++) {
            const int kc = chunk * 8;

            uint32_t af[4][4];
            #pragma unroll
            for (int fm = 0; fm < 4; fm++) {
                int mrow = warp_m + fm * 16 + g;
                const float* pa = &As[mrow * AS_STRIDE + kc + t];
                af[fm][0] = __float_as_uint(pa[0]);
                af[fm][1] = __float_as_uint(pa[8 * AS_STRIDE]);
                af[fm][2] = __float_as_uint(pa[4]);
                af[fm][3] = __float_as_uint(pa[8 * AS_STRIDE + 4]);
            }
            uint32_t bf[4][2];
            #pragma unroll
            for (int fn = 0; fn < 4; fn++) {
                const float* pb = &Bs[(kc + t) * BS_STRIDE + warp_n + fn * 8 + g];
                bf[fn][0] = __float_as_uint(pb[0]);
                bf[fn][1] = __float_as_uint(pb[4 * BS_STRIDE]);
            }

            #pragma unroll
            for (int fm = 0; fm < 4; fm++)
                #pragma unroll
                for (int fn = 0; fn < 4; fn++)
                    mma_tf32(acc[fm][fn],
                             af[fm][0], af[fm][1], af[fm][2], af[fm][3],
                             bf[fn][0], bf[fn][1]);
        }
        __syncthreads();
    }

    #pragma unroll
    for (int fm = 0; fm < 4; fm++) {
        #pragma unroll
        for (int fn = 0; fn < 4; fn++) {
            int r0 = row0 + warp_m + fm * 16 + g;
            int c0 = col0 + warp_n + fn * 8 + 2 * t;
            float2* p0 = (float2*)&C[(long)r0 * N + c0];
            *p0 = make_float2(acc[fm][fn][0], acc[fm][fn][1]);
            float2* p1 = (float2*)&C[(long)(r0 + 8) * N + c0];
            *p1 = make_float2(acc[fm][fn][2], acc[fm][fn][3]);
        }
    }
}

// ---------------- RoPE + transpose to [B,H,S,DK] ----------------
__global__ void rope_transpose_kernel(const int* __restrict__ pos,
                                      const float* __restrict__ cosT,
                                      const float* __restrict__ sinT)
{
    int idx = blockIdx.x * blockDim.x + threadIdx.x;
    int i = idx & 31;
    int h = (idx >> 5) & (HH - 1);
    int s = (idx >> 9) & (SS - 1);
    int b = idx >> 20;
    if (b >= BB) return;

    int p = pos[s];
    float c  = cosT[p * 32 + i];
    float sn = sinT[p * 32 + i];

    int src = (b * SS + s) * DD + h * DK + 2 * i;
    int dst = ((b * HH + h) * SS + s) * DK + 2 * i;

    float qe = g_Qraw[src], qo = g_Qraw[src + 1];
    g_Qh[dst]     = c * qe - sn * qo;
    g_Qh[dst + 1] = sn * qe + c * qo;

    float ke = g_Kraw[src], ko = g_Kraw[src + 1];
    g_Kh[dst]     = c * ke - sn * ko;
    g_Kh[dst + 1] = sn * ke + c * ko;

    g_Vh[dst]     = g_Vraw[src];
    g_Vh[dst + 1] = g_Vraw[src + 1];
}

// ---------------- flash attention (3xTF32 mma, causal, raw-fp32 smem) ----------------
// Br=64 (4 warps x 16 rows), Bc=32. Raw fp32 in smem, hi/lo split at frag load.
// Double-buffered cp.async K/V staging.
#define QS 68   // bank = 4g+t  (A-frag, conflict-free)
#define KS 68   // bank = 4g+t  (B-frag by row=n, conflict-free)
#define VS 72   // bank = 8t+g  (B-frag by row=k, conflict-free)
#define PS 40   // bank = 8g+t  (A-frag, conflict-free; fl2 stores conflict-free)

#define SQ  0
#define SK  (SQ + 64*QS)            // 4352, two buffers of 32*KS
#define SV  (SK + 2*32*KS)          // 8704, two buffers of 32*VS
#define SP  (SV + 2*32*VS)          // 13312
#define SMEM_FLOATS (SP + 64*PS)    // 15872 floats = 63488 B

__global__ void __launch_bounds__(128)
flash_attn_kernel()
{
    extern __shared__ float sm[];
    float* sQ = sm + SQ;
    float* sP = sm + SP;

    const int tid  = threadIdx.x;
    const int warp = tid >> 5;
    const int lane = tid & 31;
    const int g = lane >> 2;
    const int t = lane & 3;

    const int bx = gridDim.x - 1 - blockIdx.x;   // heavy tiles first
    const int bh = blockIdx.y;
    const int b = bh >> 4, h = bh & 15;
    const long base = (long)bh * SS * DK;
    const int q0 = bx * 64;

    // K/V staging assignment: each thread copies 16 contiguous floats (4x16B) per tensor
    const int s_key = tid >> 2;          // 0..31
    const int s_d0  = (tid & 3) * 16;    // 0,16,32,48
    const uint32_t kbuf0 = (uint32_t)__cvta_generic_to_shared(sm + SK) +
                           ((s_key * KS + s_d0) << 2);
    const uint32_t vbuf0 = (uint32_t)__cvta_generic_to_shared(sm + SV) +
                           ((s_key * VS + s_d0) << 2);
    const float* Kg0 = g_Kh + base + (long)s_key * DK + s_d0;
    const float* Vg0 = g_Vh + base + (long)s_key * DK + s_d0;

    // ---- stage Q once (scaled by 1/8, raw fp32) ----
    {
        const float* Qg = g_Qh + base + (long)q0 * DK;
        int row = tid >> 1;
        int d0 = (tid & 1) * 32;
        #pragma unroll
        for (int i = 0; i < 8; i++) {
            float4 v = *(const float4*)(Qg + row * 64 + d0 + i * 4);
            *(float4*)(sQ + row * QS + d0 + i * 4) =
                make_float4(v.x * 0.125f, v.y * 0.125f, v.z * 0.125f, v.w * 0.125f);
        }
    }

    // ---- prefetch tile 0 into buffer 0 ----
    {
        #pragma unroll
        for (int i = 0; i < 4; i++) cp_async16(kbuf0 + i * 16, Kg0 + i * 4);
        #pragma unroll
        for (int i = 0; i < 4; i++) cp_async16(vbuf0 + i * 16, Vg0 + i * 4);
        cp_commit();
    }

    // softmax state
    float m0 = -1e30f, m1 = -1e30f, l0 = 0.0f, l1 = 0.0f;
    float O[8][4];
    #pragma unroll
    for (int fn = 0; fn < 8; fn++)
        #pragma unroll
        for (int r = 0; r < 4; r++)
            O[fn][r] = 0.0f;

    const int pr0 = warp * 16 + g;
    const int r0g = q0 + pr0;
    const int r1g = r0g + 8;
    const int ntiles = 2 * bx + 2;

    for (int kt = 0; kt < ntiles; kt++) {
        const int cur = kt & 1;

        cp_wait<0>();       // tile kt data arrived (this thread's copies)
        __syncthreads();    // all copies visible; all warps done with the other buffer

        // ---- prefetch tile kt+1 into the other buffer (overlaps compute) ----
        if (kt + 1 < ntiles) {
            const long koff = (long)(kt + 1) * 32 * DK;
            const uint32_t kd = kbuf0 + (1 - cur) * (32 * KS * 4);
            const uint32_t vd = vbuf0 + (1 - cur) * (32 * VS * 4);
            #pragma unroll
            for (int i = 0; i < 4; i++) cp_async16(kd + i * 16, Kg0 + koff + i * 4);
            #pragma unroll
            for (int i = 0; i < 4; i++) cp_async16(vd + i * 16, Vg0 + koff + i * 4);
            cp_commit();
        }

        const float* KB = sm + SK + cur * (32 * KS);
        const float* VB = sm + SV + cur * (32 * VS);

        // ---- S = (Q/8) K^T (3xTF32, split at load) ----
        float S[4][4];
        #pragma unroll
        for (int fn = 0; fn < 4; fn++)
            #pragma unroll
            for (int r = 0; r < 4; r++)
                S[fn][r] = 0.0f;

        #pragma unroll
        for (int kc = 0; kc < 8; kc++) {
            const int k8 = kc * 8;
            const float* pa = sQ + pr0 * QS + k8 + t;
            float a0 = pa[0], a1 = pa[8 * QS], a2 = pa[4], a3 = pa[8 * QS + 4];
            float ah0 = to_tf32(a0), ah1 = to_tf32(a1), ah2 = to_tf32(a2), ah3 = to_tf32(a3);
            uint32_t uah0 = __float_as_uint(ah0), uah1 = __float_as_uint(ah1);
            uint32_t uah2 = __float_as_uint(ah2), uah3 = __float_as_uint(ah3);
            uint32_t ual0 = __float_as_uint(to_tf32(a0 - ah0));
            uint32_t ual1 = __float_as_uint(to_tf32(a1 - ah1));
            uint32_t ual2 = __float_as_uint(to_tf32(a2 - ah2));
            uint32_t ual3 = __float_as_uint(to_tf32(a3 - ah3));

            #pragma unroll
            for (int fn = 0; fn < 4; fn++) {
                const float* pb = KB + (fn * 8 + g) * KS + k8 + t;
                float b0 = pb[0], b1 = pb[4];
                float bh0 = to_tf32(b0), bh1 = to_tf32(b1);
                uint32_t ubh0 = __float_as_uint(bh0), ubh1 = __float_as_uint(bh1);
                uint32_t ubl0 = __float_as_uint(to_tf32(b0 - bh0));
                uint32_t ubl1 = __float_as_uint(to_tf32(b1 - bh1));
                mma_tf32(S[fn], uah0, uah1, uah2, uah3, ubh0, ubh1);
                mma_tf32(S[fn], uah0, uah1, uah2, uah3, ubl0, ubl1);
                mma_tf32(S[fn], ual0, ual1, ual2, ual3, ubh0, ubh1);
            }
        }

        // ---- causal mask (scale already folded into Q) ----
        const int key0 = kt * 32;
        if (kt >= 2 * bx) {
            #pragma unroll
            for (int fn = 0; fn < 4; fn++) {
                const int cg = key0 + fn * 8 + 2 * t;
                if (cg     > r0g) S[fn][0] = -1e30f;
                if (cg + 1 > r0g) S[fn][1] = -1e30f;
                if (cg     > r1g) S[fn][2] = -1e30f;
                if (cg + 1 > r1g) S[fn][3] = -1e30f;
            }
        }

        // ---- online softmax ----
        float mt0 = fmaxf(fmaxf(S[0][0], S[0][1]), fmaxf(S[1][0], S[1][1]));
        mt0 = fmaxf(mt0, fmaxf(fmaxf(S[2][0], S[2][1]), fmaxf(S[3][0], S[3][1])));
        float mt1 = fmaxf(fmaxf(S[0][2], S[0][3]), fmaxf(S[1][2], S[1][3]));
        mt1 = fmaxf(mt1, fmaxf(fmaxf(S[2][2], S[2][3]), fmaxf(S[3][2], S[3][3])));
        mt0 = fmaxf(mt0, __shfl_xor_sync(0xffffffffu, mt0, 1));
        mt0 = fmaxf(mt0, __shfl_xor_sync(0xffffffffu, mt0, 2));
        mt1 = fmaxf(mt1, __shfl_xor_sync(0xffffffffu, mt1, 1));
        mt1 = fmaxf(mt1, __shfl_xor_sync(0xffffffffu, mt1, 2));

        const float m0n = fmaxf(m0, mt0);
        const float m1n = fmaxf(m1, mt1);
        const float a0 = __expf(m0 - m0n);
        const float a1 = __expf(m1 - m1n);

        float P[4][4];
        float ps0 = 0.0f, ps1 = 0.0f;
        #pragma unroll
        for (int fn = 0; fn < 4; fn++) {
            P[fn][0] = __expf(S[fn][0] - m0n);
            P[fn][1] = __expf(S[fn][1] - m0n);
            P[fn][2] = __expf(S[fn][2] - m1n);
            P[fn][3] = __expf(S[fn][3] - m1n);
            ps0 += P[fn][0] + P[fn][1];
            ps1 += P[fn][2] + P[fn][3];
        }
        ps0 += __shfl_xor_sync(0xffffffffu, ps0, 1);
        ps0 += __shfl_xor_sync(0xffffffffu, ps0, 2);
        ps1 += __shfl_xor_sync(0xffffffffu, ps1, 1);
        ps1 += __shfl_xor_sync(0xffffffffu, ps1, 2);

        l0 = l0 * a0 + ps0;
        l1 = l1 * a1 + ps1;
        m0 = m0n;
        m1 = m1n;

        #pragma unroll
        for (int fn = 0; fn < 8; fn++) {
            O[fn][0] *= a0;
            O[fn][1] *= a0;
            O[fn][2] *= a1;
            O[fn][3] *= a1;
        }

        // ---- write P (raw fp32) to smem, warp-local rows ----
        #pragma unroll
        for (int fn = 0; fn < 4; fn++) {
            const int col = fn * 8 + 2 * t;
            *(float2*)(sP + pr0 * PS + col)       = make_float2(P[fn][0], P[fn][1]);
            *(float2*)(sP + (pr0 + 8) * PS + col) = make_float2(P[fn][2], P[fn][3]);
        }
        __syncwarp();

        // ---- O += P V (3xTF32, split at load) ----
        #pragma unroll
        for (int kc = 0; kc < 4; kc++) {
            const int k8 = kc * 8;
            const float* pa = sP + pr0 * PS + k8 + t;
            float p0 = pa[0], p1 = pa[8 * PS], p2 = pa[4], p3 = pa[8 * PS + 4];
            float ph0 = to_tf32(p0), ph1 = to_tf32(p1), ph2 = to_tf32(p2), ph3 = to_tf32(p3);
            uint32_t uah0 = __float_as_uint(ph0), uah1 = __float_as_uint(ph1);
            uint32_t uah2 = __float_as_uint(ph2), uah3 = __float_as_uint(ph3);
            uint32_t ual0 = __float_as_uint(to_tf32(p0 - ph0));
            uint32_t ual1 = __float_as_uint(to_tf32(p1 - ph1));
            uint32_t ual2 = __float_as_uint(to_tf32(p2 - ph2));
            uint32_t ual3 = __float_as_uint(to_tf32(p3 - ph3));

            #pragma unroll
            for (int fn = 0; fn < 8; fn++) {
                const float* pv = VB + (k8 + t) * VS + fn * 8 + g;
                float v0 = pv[0], v1 = pv[4 * VS];
                float vh0 = to_tf32(v0), vh1 = to_tf32(v1);
                uint32_t ubh0 = __float_as_uint(vh0), ubh1 = __float_as_uint(vh1);
                uint32_t ubl0 = __float_as_uint(to_tf32(v0 - vh0));
                uint32_t ubl1 = __float_as_uint(to_tf32(v1 - vh1));
                mma_tf32(O[fn], uah0, uah1, uah2, uah3, ubh0, ubh1);
                mma_tf32(O[fn], uah0, uah1, uah2, uah3, ubl0, ubl1);
                mma_tf32(O[fn], ual0, ual1, ual2, ual3, ubh0, ubh1);
            }
        }
    }

    // ---- epilogue: normalize + write [B,S,H*DK] ----
    const float il0 = 1.0f / l0;
    const float il1 = 1.0f / l1;
    const long o0 = ((long)(b * SS + r0g)) * DD + h * DK;
    const long o1 = ((long)(b * SS + r1g)) * DD + h * DK;
    #pragma unroll
    for (int fn = 0; fn < 8; fn++) {
        const int col = fn * 8 + 2 * t;
        *(float2*)(g_attn + o0 + col) = make_float2(O[fn][0] * il0, O[fn][1] * il0);
        *(float2*)(g_attn + o1 + col) = make_float2(O[fn][2] * il1, O[fn][3] * il1);
    }
}

// ---------------- launch ----------------
extern "C" void kernel_launch(void* const* d_in, const int* in_sizes, int n_in,
                              void* d_out, int out_size)
{
    (void)in_sizes; (void)n_in; (void)out_size;
    const float* x    = (const float*)d_in[0];
    const int*   tpos = (const int*)  d_in[1];
    const float* W_Q  = (const float*)d_in[2];
    const float* W_K  = (const float*)d_in[3];
    const float* W_V  = (const float*)d_in[4];
    const float* W_O  = (const float*)d_in[5];
    const float* cosT = (const float*)d_in[6];
    const float* sinT = (const float*)d_in[7];
    float* out = (float*)d_out;

    void *pQraw, *pKraw, *pVraw, *pAttn;
    cudaGetSymbolAddress(&pQraw, g_Qraw);
    cudaGetSymbolAddress(&pKraw, g_Kraw);
    cudaGetSymbolAddress(&pVraw, g_Vraw);
    cudaGetSymbolAddress(&pAttn, g_attn);

    static int attn_smem_set = 0;
    if (!attn_smem_set) {
        cudaFuncSetAttribute(flash_attn_kernel,
                             cudaFuncAttributeMaxDynamicSharedMemorySize,
                             SMEM_FLOATS * sizeof(float));
        attn_smem_set = 1;
    }

    dim3 gblk(256);
    dim3 ggrid(1024 / 128, MM / 128);   // (8, 32)

    gemm_tf32_kernel<<<ggrid, gblk>>>(x, W_Q, (float*)pQraw);
    gemm_tf32_kernel<<<ggrid, gblk>>>(x, W_K, (float*)pKraw);
    gemm_tf32_kernel<<<ggrid, gblk>>>(x, W_V, (float*)pVraw);

    int rope_total = BB * SS * HH * 32;
    rope_transpose_kernel<<<rope_total / 256, 256>>>(tpos, cosT, sinT);

    dim3 agrid(SS / 64, BB * HH);        // (32, 32)
    flash_attn_kernel<<<agrid, 128, SMEM_FLOATS * sizeof(float)>>>();

    gemm_tf32_kernel<<<ggrid, gblk>>>((const float*)pAttn, W_O, out);
}

// round 5
// speedup vs baseline: 4.7648x; 1.3521x over previous
#include <cuda_runtime.h>
#include <cuda_bf16.h>
#include <math.h>
#include <stdint.h>
#include <string.h>

#define BB 2
#define SS 2048
#define DD 1024
#define HH 16
#define DK 64
#define MM (BB*SS)   // 4096

// ---------------- scratch (static device memory; no allocations) ----------------
__device__ float g_Qraw[BB*SS*DD];
__device__ float g_Kraw[BB*SS*DD];
__device__ float g_Vraw[BB*SS*DD];
__device__ float g_Qh[BB*SS*DD];   // [B,H,S,DK]
__device__ float g_Kh[BB*SS*DD];
__device__ float g_Vh[BB*SS*DD];
__device__ float g_attn[BB*SS*DD]; // [B,S,D]

// ---------------- TF32 helpers (GEMMs) ----------------
__device__ __forceinline__ float to_tf32(float x) {
    float y;
    asm("cvt.rna.tf32.f32 %0, %1;" : "=f"(y) : "f"(x));
    return y;
}

__device__ __forceinline__ void mma_tf32(float c[4],
                                         uint32_t a0, uint32_t a1, uint32_t a2, uint32_t a3,
                                         uint32_t b0, uint32_t b1)
{
    asm volatile("mma.sync.aligned.m16n8k8.row.col.f32.tf32.tf32.f32 "
                 "{%0,%1,%2,%3}, {%4,%5,%6,%7}, {%8,%9}, {%0,%1,%2,%3};"
                 : "+f"(c[0]), "+f"(c[1]), "+f"(c[2]), "+f"(c[3])
                 : "r"(a0), "r"(a1), "r"(a2), "r"(a3), "r"(b0), "r"(b1));
}

// ---------------- BF16 helpers (attention) ----------------
__device__ __forceinline__ void mma_bf16(float c[4],
                                         uint32_t a0, uint32_t a1, uint32_t a2, uint32_t a3,
                                         uint32_t b0, uint32_t b1)
{
    asm volatile("mma.sync.aligned.m16n8k16.row.col.f32.bf16.bf16.f32 "
                 "{%0,%1,%2,%3}, {%4,%5,%6,%7}, {%8,%9}, {%0,%1,%2,%3};"
                 : "+f"(c[0]), "+f"(c[1]), "+f"(c[2]), "+f"(c[3])
                 : "r"(a0), "r"(a1), "r"(a2), "r"(a3), "r"(b0), "r"(b1));
}

// hi = bf16x2(x,y), lo = bf16x2(x-hi.x, y-hi.y); packed as uint32 (even in low half)
__device__ __forceinline__ void split_bf16(float x, float y, uint32_t& hi, uint32_t& lo)
{
    __nv_bfloat162 h = __floats2bfloat162_rn(x, y);
    float hx = __bfloat162float(h.x);
    float hy = __bfloat162float(h.y);
    __nv_bfloat162 l = __floats2bfloat162_rn(x - hx, y - hy);
    hi = *reinterpret_cast<uint32_t*>(&h);
    lo = *reinterpret_cast<uint32_t*>(&l);
}

// ---------------- TF32 GEMM: C[4096,1024] = A[4096,1024] @ W[1024,1024] ----------------
#define AS_STRIDE 20
#define BS_STRIDE 136

__global__ void __launch_bounds__(256, 2)
gemm_tf32_kernel(const float* __restrict__ A, const float* __restrict__ W,
                 float* __restrict__ C)
{
    const int K = 1024, N = 1024;
    __shared__ float As[128 * AS_STRIDE];
    __shared__ float Bs[16 * BS_STRIDE];

    const int tid  = threadIdx.x;
    const int warp = tid >> 5;
    const int lane = tid & 31;
    const int g = lane >> 2;
    const int t = lane & 3;

    const int wm = warp & 1;
    const int wn = warp >> 1;
    const int warp_m = wm * 64;
    const int warp_n = wn * 32;

    const int row0 = blockIdx.y * 128;
    const int col0 = blockIdx.x * 128;

    const int a_row = tid >> 1;
    const int a_cg  = (tid & 1) * 8;
    const int b_row = tid >> 4;
    const int b_col = (tid & 15) * 8;

    float acc[4][4][4];
    #pragma unroll
    for (int i = 0; i < 4; i++)
        #pragma unroll
        for (int j = 0; j < 4; j++)
            #pragma unroll
            for (int r = 0; r < 4; r++)
                acc[i][j][r] = 0.0f;

    for (int k0 = 0; k0 < K; k0 += 16) {
        {
            const float4* src = (const float4*)&A[(long)(row0 + a_row) * K + k0 + a_cg];
            float4 v0 = src[0];
            float4 v1 = src[1];
            float4 w0 = make_float4(to_tf32(v0.x), to_tf32(v0.y), to_tf32(v0.z), to_tf32(v0.w));
            float4 w1 = make_float4(to_tf32(v1.x), to_tf32(v1.y), to_tf32(v1.z), to_tf32(v1.w));
            float4* dst = (float4*)&As[a_row * AS_STRIDE + a_cg];
            dst[0] = w0;
            dst[1] = w1;
        }
        {
            const float4* src = (const float4*)&W[(long)(k0 + b_row) * N + col0 + b_col];
            float4 v0 = src[0];
            float4 v1 = src[1];
            float4 w0 = make_float4(to_tf32(v0.x), to_tf32(v0.y), to_tf32(v0.z), to_tf32(v0.w));
            float4 w1 = make_float4(to_tf32(v1.x), to_tf32(v1.y), to_tf32(v1.z), to_tf32(v1.w));
            float4* dst = (float4*)&Bs[b_row * BS_STRIDE + b_col];
            dst[0] = w0;
            dst[1] = w1;
        }
        __syncthreads();

        #pragma unroll
        for (int chunk = 0; chunk < 2; chunk++) {
            const int kc = chunk * 8;

            uint32_t af[4][4];
            #pragma unroll
            for (int fm = 0; fm < 4; fm++) {
                int mrow = warp_m + fm * 16 + g;
                const float* pa = &As[mrow * AS_STRIDE + kc + t];
                af[fm][0] = __float_as_uint(pa[0]);
                af[fm][1] = __float_as_uint(pa[8 * AS_STRIDE]);
                af[fm][2] = __float_as_uint(pa[4]);
                af[fm][3] = __float_as_uint(pa[8 * AS_STRIDE + 4]);
            }
            uint32_t bf[4][2];
            #pragma unroll
            for (int fn = 0; fn < 4; fn++) {
                const float* pb = &Bs[(kc + t) * BS_STRIDE + warp_n + fn * 8 + g];
                bf[fn][0] = __float_as_uint(pb[0]);
                bf[fn][1] = __float_as_uint(pb[4 * BS_STRIDE]);
            }

            #pragma unroll
            for (int fm = 0; fm < 4; fm++)
                #pragma unroll
                for (int fn = 0; fn < 4; fn++)
                    mma_tf32(acc[fm][fn],
                             af[fm][0], af[fm][1], af[fm][2], af[fm][3],
                             bf[fn][0], bf[fn][1]);
        }
        __syncthreads();
    }

    #pragma unroll
    for (int fm = 0; fm < 4; fm++) {
        #pragma unroll
        for (int fn = 0; fn < 4; fn++) {
            int r0 = row0 + warp_m + fm * 16 + g;
            int c0 = col0 + warp_n + fn * 8 + 2 * t;
            float2* p0 = (float2*)&C[(long)r0 * N + c0];
            *p0 = make_float2(acc[fm][fn][0], acc[fm][fn][1]);
            float2* p1 = (float2*)&C[(long)(r0 + 8) * N + c0];
            *p1 = make_float2(acc[fm][fn][2], acc[fm][fn][3]);
        }
    }
}

// ---------------- RoPE + transpose to [B,H,S,DK] ----------------
__global__ void rope_transpose_kernel(const int* __restrict__ pos,
                                      const float* __restrict__ cosT,
                                      const float* __restrict__ sinT)
{
    int idx = blockIdx.x * blockDim.x + threadIdx.x;
    int i = idx & 31;
    int h = (idx >> 5) & (HH - 1);
    int s = (idx >> 9) & (SS - 1);
    int b = idx >> 20;
    if (b >= BB) return;

    int p = pos[s];
    float c  = cosT[p * 32 + i];
    float sn = sinT[p * 32 + i];

    int src = (b * SS + s) * DD + h * DK + 2 * i;
    int dst = ((b * HH + h) * SS + s) * DK + 2 * i;

    float qe = g_Qraw[src], qo = g_Qraw[src + 1];
    g_Qh[dst]     = c * qe - sn * qo;
    g_Qh[dst + 1] = sn * qe + c * qo;

    float ke = g_Kraw[src], ko = g_Kraw[src + 1];
    g_Kh[dst]     = c * ke - sn * ko;
    g_Kh[dst + 1] = sn * ke + c * ko;

    g_Vh[dst]     = g_Vraw[src];
    g_Vh[dst + 1] = g_Vraw[src + 1];
}

// ---------------- flash attention (3xBF16 mma m16n8k16, causal) ----------------
// Br=64 (4 warps x 16 rows), Bc=32. All operands pre-split into packed bf16x2
// hi/lo planes in smem at staging time. XOR-swizzled, conflict-free layouts.
//
// smem word map (uint32):
//  sQ : [pl][64 rows][32 w]  idx = pl*2048 + (r<<5) + (w ^ ((r&7)<<2))          @ 0
//  sK : [buf][pl][32 r][32 w] idx = 4096 + buf*2048 + pl*1024 + (r<<5) + (w^((r&7)<<2))
//  sVT: [buf][pl][64 n][16 kp] idx = 8192 + buf*2048 + pl*1024 + (n<<4) + (kp^(((n>>1)&3)<<2))
//  sP : [pl][64 r][16 kp]     idx = 12288 + pl*1024 + (r<<4) + (kp^(((r>>1)&3)<<2))
#define ATT_SMEM_WORDS 14336   // 57344 bytes

__global__ void __launch_bounds__(128, 3)
flash_attn_kernel()
{
    extern __shared__ uint32_t smw[];

    const int tid  = threadIdx.x;
    const int warp = tid >> 5;
    const int lane = tid & 31;
    const int g = lane >> 2;
    const int t = lane & 3;

    const int bx = gridDim.x - 1 - blockIdx.x;   // heavy tiles first
    const int bh = blockIdx.y;
    const int b = bh >> 4, h = bh & 15;
    const long base = (long)bh * SS * DK;
    const int q0 = bx * 64;

    // ---- stage Q once (scaled by 1/8, bf16 hi/lo planes) ----
    {
        const float* Qg = g_Qh + base + (long)q0 * DK;
        const int row = tid >> 1;
        #pragma unroll
        for (int s = 0; s < 16; s++) {
            const int w = (tid & 1) + 2 * s;
            float2 v = *(const float2*)(Qg + row * 64 + 2 * w);
            uint32_t hi, lo;
            split_bf16(v.x * 0.125f, v.y * 0.125f, hi, lo);
            const int idx = (row << 5) + (w ^ ((row & 7) << 2));
            smw[idx]        = hi;
            smw[2048 + idx] = lo;
        }
    }

    // staging thread assignments
    const int kr  = tid >> 2;         // K: row 0..31
    const int kq  = tid & 3;          // K: word phase
    const int vkp = tid >> 3;         // V: key-pair 0..15
    const int vn  = tid & 7;          // V: dim phase
    const float* Kg = g_Kh + base;
    const float* Vg = g_Vh + base;

    float2 kreg[8];
    float  va[8], vb[8];

    // prefetch tile 0 into regs
    {
        #pragma unroll
        for (int s = 0; s < 8; s++)
            kreg[s] = *(const float2*)(Kg + (long)kr * DK + 2 * kq + 8 * s);
        #pragma unroll
        for (int i = 0; i < 8; i++) {
            va[i] = Vg[(long)(2 * vkp)     * DK + vn + 8 * i];
            vb[i] = Vg[(long)(2 * vkp + 1) * DK + vn + 8 * i];
        }
    }

    // softmax state
    float m0 = -1e30f, m1 = -1e30f, l0 = 0.0f, l1 = 0.0f;
    float O[8][4];
    #pragma unroll
    for (int fn = 0; fn < 8; fn++)
        #pragma unroll
        for (int r = 0; r < 4; r++)
            O[fn][r] = 0.0f;

    const int pr0 = warp * 16 + g;
    const int r0g = q0 + pr0;
    const int r1g = r0g + 8;
    const int ntiles = 2 * bx + 2;

    const int qsw = (pr0 & 7) << 2;          // == g<<2
    const int psw = ((pr0 >> 1) & 3) << 2;   // same for pr0 and pr0+8
    const int vsw = ((g >> 1) & 3) << 2;     // V row swizzle: ((n>>1)&3)<<2 with n=fn*8+g

    for (int kt = 0; kt < ntiles; kt++) {
        const int cur = kt & 1;

        __syncthreads();   // readers of this buffer (tile kt-2) done; Q staged (kt=0)

        // ---- split + store tile kt (from regs) into smem buffer cur ----
        {
            const int kbase = 4096 + cur * 2048;
            #pragma unroll
            for (int s = 0; s < 8; s++) {
                uint32_t hi, lo;
                split_bf16(kreg[s].x, kreg[s].y, hi, lo);
                const int w = kq + 4 * s;
                const int idx = kbase + (kr << 5) + (w ^ ((kr & 7) << 2));
                smw[idx]        = hi;
                smw[idx + 1024] = lo;
            }
            const int vbase = 8192 + cur * 2048;
            #pragma unroll
            for (int i = 0; i < 8; i++) {
                uint32_t hi, lo;
                split_bf16(va[i], vb[i], hi, lo);
                const int n = vn + 8 * i;
                const int idx = vbase + (n << 4) + (vkp ^ (((n >> 1) & 3) << 2));
                smw[idx]        = hi;
                smw[idx + 1024] = lo;
            }
        }
        __syncthreads();

        // ---- prefetch tile kt+1 into regs (overlaps all compute below) ----
        if (kt + 1 < ntiles) {
            const long koff = (long)(kt + 1) * 32 * DK;
            #pragma unroll
            for (int s = 0; s < 8; s++)
                kreg[s] = *(const float2*)(Kg + koff + (long)kr * DK + 2 * kq + 8 * s);
            #pragma unroll
            for (int i = 0; i < 8; i++) {
                va[i] = Vg[koff + (long)(2 * vkp)     * DK + vn + 8 * i];
                vb[i] = Vg[koff + (long)(2 * vkp + 1) * DK + vn + 8 * i];
            }
        }

        // ---- S = (Q/8) K^T  (3xBF16, k16) ----
        float S[4][4];
        #pragma unroll
        for (int fn = 0; fn < 4; fn++)
            #pragma unroll
            for (int r = 0; r < 4; r++)
                S[fn][r] = 0.0f;

        const int kbase = 4096 + cur * 2048;
        #pragma unroll
        for (int kc = 0; kc < 4; kc++) {
            const int w0 = kc * 8 + t;
            const int i00 = (pr0 << 5) + (w0 ^ qsw);
            const int i01 = ((pr0 + 8) << 5) + (w0 ^ qsw);
            const int i10 = (pr0 << 5) + ((w0 + 4) ^ qsw);
            const int i11 = ((pr0 + 8) << 5) + ((w0 + 4) ^ qsw);
            const uint32_t ah0 = smw[i00], ah1 = smw[i01], ah2 = smw[i10], ah3 = smw[i11];
            const uint32_t al0 = smw[2048 + i00], al1 = smw[2048 + i01];
            const uint32_t al2 = smw[2048 + i10], al3 = smw[2048 + i11];

            #pragma unroll
            for (int fn = 0; fn < 4; fn++) {
                const int n = fn * 8 + g;
                const int j0 = kbase + (n << 5) + (w0 ^ qsw);        // (n&7)==g
                const int j1 = kbase + (n << 5) + ((w0 + 4) ^ qsw);
                const uint32_t bh0 = smw[j0], bh1 = smw[j1];
                const uint32_t bl0 = smw[j0 + 1024], bl1 = smw[j1 + 1024];
                mma_bf16(S[fn], ah0, ah1, ah2, ah3, bh0, bh1);
                mma_bf16(S[fn], ah0, ah1, ah2, ah3, bl0, bl1);
                mma_bf16(S[fn], al0, al1, al2, al3, bh0, bh1);
            }
        }

        // ---- causal mask ----
        const int key0 = kt * 32;
        if (kt >= 2 * bx) {
            #pragma unroll
            for (int fn = 0; fn < 4; fn++) {
                const int cg = key0 + fn * 8 + 2 * t;
                if (cg     > r0g) S[fn][0] = -1e30f;
                if (cg + 1 > r0g) S[fn][1] = -1e30f;
                if (cg     > r1g) S[fn][2] = -1e30f;
                if (cg + 1 > r1g) S[fn][3] = -1e30f;
            }
        }

        // ---- online softmax ----
        float mt0 = fmaxf(fmaxf(S[0][0], S[0][1]), fmaxf(S[1][0], S[1][1]));
        mt0 = fmaxf(mt0, fmaxf(fmaxf(S[2][0], S[2][1]), fmaxf(S[3][0], S[3][1])));
        float mt1 = fmaxf(fmaxf(S[0][2], S[0][3]), fmaxf(S[1][2], S[1][3]));
        mt1 = fmaxf(mt1, fmaxf(fmaxf(S[2][2], S[2][3]), fmaxf(S[3][2], S[3][3])));
        mt0 = fmaxf(mt0, __shfl_xor_sync(0xffffffffu, mt0, 1));
        mt0 = fmaxf(mt0, __shfl_xor_sync(0xffffffffu, mt0, 2));
        mt1 = fmaxf(mt1, __shfl_xor_sync(0xffffffffu, mt1, 1));
        mt1 = fmaxf(mt1, __shfl_xor_sync(0xffffffffu, mt1, 2));

        const float m0n = fmaxf(m0, mt0);
        const float m1n = fmaxf(m1, mt1);
        const float a0 = __expf(m0 - m0n);
        const float a1 = __expf(m1 - m1n);

        float P[4][4];
        float ps0 = 0.0f, ps1 = 0.0f;
        #pragma unroll
        for (int fn = 0; fn < 4; fn++) {
            P[fn][0] = __expf(S[fn][0] - m0n);
            P[fn][1] = __expf(S[fn][1] - m0n);
            P[fn][2] = __expf(S[fn][2] - m1n);
            P[fn][3] = __expf(S[fn][3] - m1n);
            ps0 += P[fn][0] + P[fn][1];
            ps1 += P[fn][2] + P[fn][3];
        }
        ps0 += __shfl_xor_sync(0xffffffffu, ps0, 1);
        ps0 += __shfl_xor_sync(0xffffffffu, ps0, 2);
        ps1 += __shfl_xor_sync(0xffffffffu, ps1, 1);
        ps1 += __shfl_xor_sync(0xffffffffu, ps1, 2);

        l0 = l0 * a0 + ps0;
        l1 = l1 * a1 + ps1;
        m0 = m0n;
        m1 = m1n;

        #pragma unroll
        for (int fn = 0; fn < 8; fn++) {
            O[fn][0] *= a0;
            O[fn][1] *= a0;
            O[fn][2] *= a1;
            O[fn][3] *= a1;
        }

        // ---- split + store P (bf16 hi/lo planes, warp-local rows) ----
        #pragma unroll
        for (int fn = 0; fn < 4; fn++) {
            uint32_t hi0, lo0, hi1, lo1;
            split_bf16(P[fn][0], P[fn][1], hi0, lo0);
            split_bf16(P[fn][2], P[fn][3], hi1, lo1);
            const int kp = fn * 4 + t;
            const int i0 = 12288 + (pr0 << 4) + (kp ^ psw);
            const int i1 = 12288 + ((pr0 + 8) << 4) + (kp ^ psw);
            smw[i0]        = hi0;
            smw[i0 + 1024] = lo0;
            smw[i1]        = hi1;
            smw[i1 + 1024] = lo1;
        }
        __syncwarp();

        // ---- O += P V  (3xBF16, k16, V pre-transposed) ----
        const int vbase = 8192 + cur * 2048;
        #pragma unroll
        for (int kc = 0; kc < 2; kc++) {
            const int w0 = kc * 8 + t;
            const int i00 = 12288 + (pr0 << 4) + (w0 ^ psw);
            const int i01 = 12288 + ((pr0 + 8) << 4) + (w0 ^ psw);
            const int i10 = 12288 + (pr0 << 4) + ((w0 + 4) ^ psw);
            const int i11 = 12288 + ((pr0 + 8) << 4) + ((w0 + 4) ^ psw);
            const uint32_t ah0 = smw[i00], ah1 = smw[i01], ah2 = smw[i10], ah3 = smw[i11];
            const uint32_t al0 = smw[1024 + i00], al1 = smw[1024 + i01];
            const uint32_t al2 = smw[1024 + i10], al3 = smw[1024 + i11];

            #pragma unroll
            for (int fn = 0; fn < 8; fn++) {
                const int n = fn * 8 + g;
                const int j0 = vbase + (n << 4) + (w0 ^ vsw);
                const int j1 = vbase + (n << 4) + ((w0 + 4) ^ vsw);
                const uint32_t bh0 = smw[j0], bh1 = smw[j1];
                const uint32_t bl0 = smw[j0 + 1024], bl1 = smw[j1 + 1024];
                mma_bf16(O[fn], ah0, ah1, ah2, ah3, bh0, bh1);
                mma_bf16(O[fn], ah0, ah1, ah2, ah3, bl0, bl1);
                mma_bf16(O[fn], al0, al1, al2, al3, bh0, bh1);
            }
        }
    }

    // ---- epilogue: normalize + write [B,S,H*DK] ----
    const float il0 = 1.0f / l0;
    const float il1 = 1.0f / l1;
    const long o0 = ((long)(b * SS + r0g)) * DD + h * DK;
    const long o1 = ((long)(b * SS + r1g)) * DD + h * DK;
    #pragma unroll
    for (int fn = 0; fn < 8; fn++) {
        const int col = fn * 8 + 2 * t;
        *(float2*)(g_attn + o0 + col) = make_float2(O[fn][0] * il0, O[fn][1] * il0);
        *(float2*)(g_attn + o1 + col) = make_float2(O[fn][2] * il1, O[fn][3] * il1);
    }
}

// ---------------- launch ----------------
extern "C" void kernel_launch(void* const* d_in, const int* in_sizes, int n_in,
                              void* d_out, int out_size)
{
    (void)in_sizes; (void)n_in; (void)out_size;
    const float* x    = (const float*)d_in[0];
    const int*   tpos = (const int*)  d_in[1];
    const float* W_Q  = (const float*)d_in[2];
    const float* W_K  = (const float*)d_in[3];
    const float* W_V  = (const float*)d_in[4];
    const float* W_O  = (const float*)d_in[5];
    const float* cosT = (const float*)d_in[6];
    const float* sinT = (const float*)d_in[7];
    float* out = (float*)d_out;

    void *pQraw, *pKraw, *pVraw, *pAttn;
    cudaGetSymbolAddress(&pQraw, g_Qraw);
    cudaGetSymbolAddress(&pKraw, g_Kraw);
    cudaGetSymbolAddress(&pVraw, g_Vraw);
    cudaGetSymbolAddress(&pAttn, g_attn);

    static int attn_smem_set = 0;
    if (!attn_smem_set) {
        cudaFuncSetAttribute(flash_attn_kernel,
                             cudaFuncAttributeMaxDynamicSharedMemorySize,
                             ATT_SMEM_WORDS * sizeof(uint32_t));
        attn_smem_set = 1;
    }

    dim3 gblk(256);
    dim3 ggrid(1024 / 128, MM / 128);   // (8, 32)

    gemm_tf32_kernel<<<ggrid, gblk>>>(x, W_Q, (float*)pQraw);
    gemm_tf32_kernel<<<ggrid, gblk>>>(x, W_K, (float*)pKraw);
    gemm_tf32_kernel<<<ggrid, gblk>>>(x, W_V, (float*)pVraw);

    int rope_total = BB * SS * HH * 32;
    rope_transpose_kernel<<<rope_total / 256, 256>>>(tpos, cosT, sinT);

    dim3 agrid(SS / 64, BB * HH);        // (32, 32)
    flash_attn_kernel<<<agrid, 128, ATT_SMEM_WORDS * sizeof(uint32_t)>>>();

    gemm_tf32_kernel<<<ggrid, gblk>>>((const float*)pAttn, W_O, out);
}